// round 16
// baseline (speedup 1.0000x reference)
#include <cuda_runtime.h>

// Round 16: full-tensor attention. QK mma (R15-proven) + PV mma with P split
// at softmax-write time and V staged transposed+split (fragment addressing
// identical to QK's proven mapping). O lives in mma fragments -> key-split
// merge epilogue deleted. Projections = R11/R15 exact (measured best).

#define EMBED 1024
#define NHEAD 16
#define HDIM  64
#define BATCH 2
#define SEQ   2048
#define MTOT  (BATCH*SEQ)

#define PBM 128
#define PBN 128
#define PBK 16
#define PADT 136

#define PADP 68
#define ATTN_FLOATS (6*64*PADP + 128)   // Qhi,Qlo,KVhi,KVlo,Phi,Plo + corr/l
#define ATTN_SMEM   (ATTN_FLOATS*4)

typedef unsigned long long u64;
typedef unsigned int u32;

// ---- tf32 helpers ----
__device__ __forceinline__ void split_tf32(float a, u32& hi, u32& lo) {
    asm("cvt.rna.tf32.f32 %0, %1;" : "=r"(hi) : "f"(a));
    float r = a - __uint_as_float(hi);
    asm("cvt.rna.tf32.f32 %0, %1;" : "=r"(lo) : "f"(r));
}
__device__ __forceinline__ void mma8(float* c, const u32* a, const u32* b) {
    asm("mma.sync.aligned.m16n8k8.row.col.f32.tf32.tf32.f32 "
        "{%0,%1,%2,%3}, {%4,%5,%6,%7}, {%8,%9}, {%0,%1,%2,%3};"
        : "+f"(c[0]), "+f"(c[1]), "+f"(c[2]), "+f"(c[3])
        : "r"(a[0]), "r"(a[1]), "r"(a[2]), "r"(a[3]), "r"(b[0]), "r"(b[1]));
}

__device__ float g_q[BATCH*NHEAD*SEQ*HDIM];
__device__ float g_k[BATCH*NHEAD*SEQ*HDIM];
__device__ float g_v[BATCH*NHEAD*SEQ*HDIM];
__device__ float g_h[MTOT*EMBED];

// ---------------------------------------------------------------------------
// R11 projection GEMM body (measured best): split at STS time, scalar smem.
// ---------------------------------------------------------------------------
#define STS_SPLIT(DH, DL, J, V)                                                \
    { u32 _h, _l; split_tf32((V), _h, _l);                                     \
      DH[lc8+(J)][lr] = _h; DL[lc8+(J)][lr] = _l; }

#define PROJ_MMA_BODY(APTR, WPTR)                                              \
    __shared__ u32 Ash[PBK][PADT];                                             \
    __shared__ u32 Asl[PBK][PADT];                                             \
    __shared__ u32 Bsh[PBK][PADT];                                             \
    __shared__ u32 Bsl[PBK][PADT];                                             \
    const int tid  = threadIdx.x;                                              \
    const int lane = tid & 31;                                                 \
    const int wid  = tid >> 5;                                                 \
    const int m0 = blockIdx.y * PBM;                                           \
    const int n0 = blockIdx.x * PBN;                                           \
    const int wm = (wid >> 2) << 6;                                            \
    const int wn = (wid & 3) << 5;                                             \
    const int g4 = lane >> 2;                                                  \
    const int t4 = lane & 3;                                                   \
    const int lr  = tid >> 1;                                                  \
    const int lc8 = (tid & 1) << 3;                                            \
    const float* Ap = (APTR) + (size_t)(m0 + lr) * EMBED + lc8;                \
    const float* Wp = (WPTR) + (size_t)(n0 + lr) * EMBED + lc8;                \
    float c[4][4][4];                                                          \
    _Pragma("unroll")                                                          \
    for (int mi = 0; mi < 4; mi++)                                             \
        _Pragma("unroll")                                                      \
        for (int ni = 0; ni < 4; ni++)                                         \
            _Pragma("unroll")                                                  \
            for (int u = 0; u < 4; u++) c[mi][ni][u] = 0.f;                    \
    float4 a0 = *(const float4*)(Ap);                                          \
    float4 a1 = *(const float4*)(Ap + 4);                                      \
    float4 w0 = *(const float4*)(Wp);                                          \
    float4 w1 = *(const float4*)(Wp + 4);                                      \
    for (int kb = 0; kb < EMBED; kb += PBK) {                                  \
        __syncthreads();                                                       \
        STS_SPLIT(Ash, Asl, 0, a0.x)  STS_SPLIT(Ash, Asl, 1, a0.y)             \
        STS_SPLIT(Ash, Asl, 2, a0.z)  STS_SPLIT(Ash, Asl, 3, a0.w)             \
        STS_SPLIT(Ash, Asl, 4, a1.x)  STS_SPLIT(Ash, Asl, 5, a1.y)             \
        STS_SPLIT(Ash, Asl, 6, a1.z)  STS_SPLIT(Ash, Asl, 7, a1.w)             \
        STS_SPLIT(Bsh, Bsl, 0, w0.x)  STS_SPLIT(Bsh, Bsl, 1, w0.y)             \
        STS_SPLIT(Bsh, Bsl, 2, w0.z)  STS_SPLIT(Bsh, Bsl, 3, w0.w)             \
        STS_SPLIT(Bsh, Bsl, 4, w1.x)  STS_SPLIT(Bsh, Bsl, 5, w1.y)             \
        STS_SPLIT(Bsh, Bsl, 6, w1.z)  STS_SPLIT(Bsh, Bsl, 7, w1.w)             \
        __syncthreads();                                                       \
        if (kb + PBK < EMBED) {                                                \
            a0 = *(const float4*)(Ap + kb + PBK);                              \
            a1 = *(const float4*)(Ap + kb + PBK + 4);                          \
            w0 = *(const float4*)(Wp + kb + PBK);                              \
            w1 = *(const float4*)(Wp + kb + PBK + 4);                          \
        }                                                                      \
        _Pragma("unroll")                                                      \
        for (int k8 = 0; k8 < PBK; k8 += 8) {                                  \
            u32 bhi[4][2], blo[4][2];                                          \
            _Pragma("unroll")                                                  \
            for (int ni = 0; ni < 4; ni++) {                                   \
                const int kc = wn + ni*8 + g4;                                 \
                bhi[ni][0] = Bsh[k8 + t4    ][kc];                             \
                bhi[ni][1] = Bsh[k8 + t4 + 4][kc];                             \
                blo[ni][0] = Bsl[k8 + t4    ][kc];                             \
                blo[ni][1] = Bsl[k8 + t4 + 4][kc];                             \
            }                                                                  \
            _Pragma("unroll")                                                  \
            for (int mi = 0; mi < 4; mi++) {                                   \
                const int r = wm + mi*16 + g4;                                 \
                u32 ahi[4], alo[4];                                            \
                ahi[0] = Ash[k8 + t4    ][r];                                  \
                ahi[1] = Ash[k8 + t4    ][r + 8];                              \
                ahi[2] = Ash[k8 + t4 + 4][r];                                  \
                ahi[3] = Ash[k8 + t4 + 4][r + 8];                              \
                alo[0] = Asl[k8 + t4    ][r];                                  \
                alo[1] = Asl[k8 + t4    ][r + 8];                              \
                alo[2] = Asl[k8 + t4 + 4][r];                                  \
                alo[3] = Asl[k8 + t4 + 4][r + 8];                              \
                _Pragma("unroll")                                              \
                for (int ni = 0; ni < 4; ni++) {                               \
                    mma8(c[mi][ni], ahi, bhi[ni]);                             \
                    mma8(c[mi][ni], ahi, blo[ni]);                             \
                    mma8(c[mi][ni], alo, bhi[ni]);                             \
                }                                                              \
            }                                                                  \
        }                                                                      \
    }

// ---------------------------------------------------------------------------
__global__ __launch_bounds__(256, 2) void qkv_proj_kernel(
    const float* __restrict__ X,
    const float* __restrict__ Wq, const float* __restrict__ bq,
    const float* __restrict__ Wk, const float* __restrict__ bk,
    const float* __restrict__ Wv, const float* __restrict__ bv)
{
    const int z = blockIdx.z;
    const float *W, *bias; float* Out;
    if (z == 0)      { W = Wq; bias = bq; Out = g_q; }
    else if (z == 1) { W = Wk; bias = bk; Out = g_k; }
    else             { W = Wv; bias = bv; Out = g_v; }

    PROJ_MMA_BODY(X, W)

#pragma unroll
    for (int mi = 0; mi < 4; mi++) {
#pragma unroll
        for (int ni = 0; ni < 4; ni++) {
            const int col = n0 + wn + ni*8 + 2*t4;
            const int h   = col >> 6;
            const int d   = col & 63;
            float2 bb = *(const float2*)&bias[col];
#pragma unroll
            for (int half = 0; half < 2; half++) {
                int row = m0 + wm + mi*16 + g4 + half*8;
                int b   = row >> 11;
                int n   = row & (SEQ - 1);
                float2 o = make_float2(c[mi][ni][2*half+0] + bb.x,
                                       c[mi][ni][2*half+1] + bb.y);
                *(float2*)&Out[((size_t)(b*NHEAD + h)*SEQ + n)*HDIM + d] = o;
            }
        }
    }
}

// ---------------------------------------------------------------------------
__global__ __launch_bounds__(256, 2) void out_proj_kernel(
    const float* __restrict__ Wo, const float* __restrict__ bo,
    float* __restrict__ Outp)
{
    PROJ_MMA_BODY(g_h, Wo)

#pragma unroll
    for (int mi = 0; mi < 4; mi++) {
#pragma unroll
        for (int ni = 0; ni < 4; ni++) {
            const int col = n0 + wn + ni*8 + 2*t4;
            float2 bb = *(const float2*)&bo[col];
#pragma unroll
            for (int half = 0; half < 2; half++) {
                int row = m0 + wm + mi*16 + g4 + half*8;
                float2 o = make_float2(c[mi][ni][2*half+0] + bb.x,
                                       c[mi][ni][2*half+1] + bb.y);
                *(float2*)&Outp[(size_t)row * EMBED + col] = o;
            }
        }
    }
}

// ---------------------------------------------------------------------------
// Full-tensor flash attention.
// Smem: Qhi,Qlo [q][d] | KVhi,KVlo: K [key][d], then Vt [d][key] | Phi,Plo
// (raw S floats, then P splits) | corr_s, l_s.
// 8 warps = 4(m over q) x 2(n: keys for QK / d for PV). 4 barriers/tile.
// ---------------------------------------------------------------------------
__global__ __launch_bounds__(256, 2) void attn_kernel()
{
    extern __shared__ float sm[];
    u32*   Qhi  = (u32*)sm;
    u32*   Qlo  = (u32*)(sm + 64*PADP);
    u32*   KVhi = (u32*)(sm + 2*64*PADP);
    u32*   KVlo = (u32*)(sm + 3*64*PADP);
    u32*   Phi  = (u32*)(sm + 4*64*PADP);
    u32*   Plo  = (u32*)(sm + 5*64*PADP);
    float* Sf   = (float*)Phi;            // raw S view
    float* corr_s = sm + 6*64*PADP;
    float* l_s    = corr_s + 64;

    const int tid  = threadIdx.x;
    const int lane = tid & 31;
    const int wid  = tid >> 5;
    const int bh  = blockIdx.y;
    const int q0  = blockIdx.x << 6;
    const size_t base = (size_t)bh * SEQ * HDIM;
    const float* Qg = g_q + base;
    const float* Kg = g_k + base;
    const float* Vg = g_v + base;

    const int lr = tid >> 2;           // staging row 0..63
    const int dq = (tid & 3) << 4;     // staging d-offset (16 elems)
    const int ty = tid >> 4;           // softmax mapping
    const int tx = tid & 15;
    // mma mapping: 8 warps = 4(m) x 2(n)
    const int qm0 = (wid >> 1) << 4;
    const int wn  = (wid & 1) << 5;
    const int g4  = lane >> 2;
    const int t4  = lane & 3;

    // Stage Q once: fp32 load, split -> Qhi/Qlo [q][d]
#pragma unroll
    for (int it = 0; it < 4; it++) {
        float4 v = *(const float4*)&Qg[(size_t)(q0 + lr)*HDIM + dq + it*4];
        uint4 h, l;
        split_tf32(v.x, h.x, l.x); split_tf32(v.y, h.y, l.y);
        split_tf32(v.z, h.z, l.z); split_tf32(v.w, h.w, l.w);
        *(uint4*)&Qhi[lr*PADP + dq + it*4] = h;
        *(uint4*)&Qlo[lr*PADP + dq + it*4] = l;
    }

    float m_run[4], l_run[4];
#pragma unroll
    for (int i = 0; i < 4; i++) { m_run[i] = -1e30f; l_run[i] = 0.f; }
    float co[4][4];                    // O fragments: rows qm0+g4(+8), d cols wn+ni*8+2t4
#pragma unroll
    for (int ni = 0; ni < 4; ni++)
#pragma unroll
        for (int u = 0; u < 4; u++) co[ni][u] = 0.f;

    for (int k0 = 0; k0 < SEQ; k0 += 64) {
        __syncthreads();   // (1) prev PV done (KV, P free); Q staged (iter 0)
        // Stage K: split -> KVhi/KVlo [key][d]
#pragma unroll
        for (int it = 0; it < 4; it++) {
            float4 v = *(const float4*)&Kg[(size_t)(k0 + lr)*HDIM + dq + it*4];
            uint4 h, l;
            split_tf32(v.x, h.x, l.x); split_tf32(v.y, h.y, l.y);
            split_tf32(v.z, h.z, l.z); split_tf32(v.w, h.w, l.w);
            *(uint4*)&KVhi[lr*PADP + dq + it*4] = h;
            *(uint4*)&KVlo[lr*PADP + dq + it*4] = l;
        }
        __syncthreads();   // (2) K ready

        // ---- S = Q K^T via 3xTF32 mma ----
        float c[4][4];
#pragma unroll
        for (int ni = 0; ni < 4; ni++)
#pragma unroll
            for (int u = 0; u < 4; u++) c[ni][u] = 0.f;

#pragma unroll
        for (int k8 = 0; k8 < 64; k8 += 8) {
            u32 ahi[4], alo[4];
            ahi[0] = Qhi[(qm0+g4  )*PADP + k8 + t4    ];
            ahi[1] = Qhi[(qm0+g4+8)*PADP + k8 + t4    ];
            ahi[2] = Qhi[(qm0+g4  )*PADP + k8 + t4 + 4];
            ahi[3] = Qhi[(qm0+g4+8)*PADP + k8 + t4 + 4];
            alo[0] = Qlo[(qm0+g4  )*PADP + k8 + t4    ];
            alo[1] = Qlo[(qm0+g4+8)*PADP + k8 + t4    ];
            alo[2] = Qlo[(qm0+g4  )*PADP + k8 + t4 + 4];
            alo[3] = Qlo[(qm0+g4+8)*PADP + k8 + t4 + 4];
#pragma unroll
            for (int ni = 0; ni < 4; ni++) {
                const int kr = wn + ni*8 + g4;
                u32 bhi[2], blo[2];
                bhi[0] = KVhi[kr*PADP + k8 + t4];
                bhi[1] = KVhi[kr*PADP + k8 + t4 + 4];
                blo[0] = KVlo[kr*PADP + k8 + t4];
                blo[1] = KVlo[kr*PADP + k8 + t4 + 4];
                mma8(c[ni], ahi, bhi);
                mma8(c[ni], ahi, blo);
                mma8(c[ni], alo, bhi);
            }
        }
        // write raw S floats into Phi region
#pragma unroll
        for (int ni = 0; ni < 4; ni++) {
            const int col = wn + ni*8 + 2*t4;
            *(float2*)&Sf[(qm0+g4  )*PADP + col] = make_float2(c[ni][0], c[ni][1]);
            *(float2*)&Sf[(qm0+g4+8)*PADP + col] = make_float2(c[ni][2], c[ni][3]);
        }
        __syncthreads();   // (3) S complete; K region free

        // ---- softmax: read raw S, write split P (in place) ----
#pragma unroll
        for (int i = 0; i < 4; i++) {
            const int row = (ty<<2) + i;
            float4 sv = *(const float4*)&Sf[row*PADP + (tx<<2)];
            float s[4] = {sv.x*8.0f, sv.y*8.0f, sv.z*8.0f, sv.w*8.0f};
            float mx = fmaxf(fmaxf(s[0], s[1]), fmaxf(s[2], s[3]));
            mx = fmaxf(mx, __shfl_xor_sync(0xffffffffu, mx, 8, 16));
            mx = fmaxf(mx, __shfl_xor_sync(0xffffffffu, mx, 4, 16));
            mx = fmaxf(mx, __shfl_xor_sync(0xffffffffu, mx, 2, 16));
            mx = fmaxf(mx, __shfl_xor_sync(0xffffffffu, mx, 1, 16));
            float mnew = fmaxf(m_run[i], mx);
            float corr = __expf(m_run[i] - mnew);
            float rs = 0.f;
            uint4 ph, pl;
            u32* php = (u32*)&ph; u32* plp = (u32*)&pl;
#pragma unroll
            for (int j = 0; j < 4; j++) {
                float p = __expf(s[j] - mnew);
                rs += p;
                split_tf32(p, php[j], plp[j]);
            }
            rs += __shfl_xor_sync(0xffffffffu, rs, 8, 16);
            rs += __shfl_xor_sync(0xffffffffu, rs, 4, 16);
            rs += __shfl_xor_sync(0xffffffffu, rs, 2, 16);
            rs += __shfl_xor_sync(0xffffffffu, rs, 1, 16);
            l_run[i] = l_run[i] * corr + rs;
            m_run[i] = mnew;
            if (tx == 0) corr_s[row] = corr;
            *(uint4*)&Phi[row*PADP + (tx<<2)] = ph;
            *(uint4*)&Plo[row*PADP + (tx<<2)] = pl;
        }
        // Stage Vt transposed split into KV buffers: Vt[d][key]
#pragma unroll
        for (int it = 0; it < 4; it++) {
            float4 v = *(const float4*)&Vg[(size_t)(k0 + lr)*HDIM + dq + it*4];
            u32 h, l;
            int d = dq + it*4;
            split_tf32(v.x, h, l); KVhi[(d+0)*PADP + lr] = h; KVlo[(d+0)*PADP + lr] = l;
            split_tf32(v.y, h, l); KVhi[(d+1)*PADP + lr] = h; KVlo[(d+1)*PADP + lr] = l;
            split_tf32(v.z, h, l); KVhi[(d+2)*PADP + lr] = h; KVlo[(d+2)*PADP + lr] = l;
            split_tf32(v.w, h, l); KVhi[(d+3)*PADP + lr] = h; KVlo[(d+3)*PADP + lr] = l;
        }
        __syncthreads();   // (4) P splits, corr, Vt ready

        // ---- correct O fragments, then O += P V via 3xTF32 mma ----
        {
            float c0 = corr_s[qm0 + g4];
            float c1 = corr_s[qm0 + g4 + 8];
#pragma unroll
            for (int ni = 0; ni < 4; ni++) {
                co[ni][0] *= c0; co[ni][1] *= c0;
                co[ni][2] *= c1; co[ni][3] *= c1;
            }
        }
#pragma unroll
        for (int k8 = 0; k8 < 64; k8 += 8) {
            u32 ahi[4], alo[4];
            ahi[0] = Phi[(qm0+g4  )*PADP + k8 + t4    ];
            ahi[1] = Phi[(qm0+g4+8)*PADP + k8 + t4    ];
            ahi[2] = Phi[(qm0+g4  )*PADP + k8 + t4 + 4];
            ahi[3] = Phi[(qm0+g4+8)*PADP + k8 + t4 + 4];
            alo[0] = Plo[(qm0+g4  )*PADP + k8 + t4    ];
            alo[1] = Plo[(qm0+g4+8)*PADP + k8 + t4    ];
            alo[2] = Plo[(qm0+g4  )*PADP + k8 + t4 + 4];
            alo[3] = Plo[(qm0+g4+8)*PADP + k8 + t4 + 4];
#pragma unroll
            for (int ni = 0; ni < 4; ni++) {
                const int dr = wn + ni*8 + g4;
                u32 bhi[2], blo[2];
                bhi[0] = KVhi[dr*PADP + k8 + t4];
                bhi[1] = KVhi[dr*PADP + k8 + t4 + 4];
                blo[0] = KVlo[dr*PADP + k8 + t4];
                blo[1] = KVlo[dr*PADP + k8 + t4 + 4];
                mma8(co[ni], ahi, bhi);
                mma8(co[ni], ahi, blo);
                mma8(co[ni], alo, bhi);
            }
        }
    }

    // publish l, then write O fragments normalized
    if (tx == 0) {
#pragma unroll
        for (int i = 0; i < 4; i++) l_s[(ty<<2)+i] = l_run[i];
    }
    __syncthreads();

    {
        const int b = bh >> 4;
        const int h = bh & 15;
        float inv0 = 1.0f / l_s[qm0 + g4];
        float inv1 = 1.0f / l_s[qm0 + g4 + 8];
        int r0 = q0 + qm0 + g4;
        int r1 = r0 + 8;
        float* dst0 = &g_h[((size_t)(b*SEQ + r0))*EMBED + h*HDIM];
        float* dst1 = &g_h[((size_t)(b*SEQ + r1))*EMBED + h*HDIM];
#pragma unroll
        for (int ni = 0; ni < 4; ni++) {
            const int col = wn + ni*8 + 2*t4;
            *(float2*)&dst0[col] = make_float2(co[ni][0]*inv0, co[ni][1]*inv0);
            *(float2*)&dst1[col] = make_float2(co[ni][2]*inv1, co[ni][3]*inv1);
        }
    }
}

// ---------------------------------------------------------------------------
extern "C" void kernel_launch(void* const* d_in, const int* in_sizes, int n_in,
                              void* d_out, int out_size)
{
    const float* x  = (const float*)d_in[0];
    const float* Wq = (const float*)d_in[1];
    const float* bq = (const float*)d_in[2];
    const float* Wk = (const float*)d_in[3];
    const float* bk = (const float*)d_in[4];
    const float* Wv = (const float*)d_in[5];
    const float* bv = (const float*)d_in[6];
    const float* Wo = (const float*)d_in[7];
    const float* bo = (const float*)d_in[8];
    float* out = (float*)d_out;

    cudaFuncSetAttribute(attn_kernel,
                         cudaFuncAttributeMaxDynamicSharedMemorySize, ATTN_SMEM);

    dim3 gproj(EMBED / PBN, MTOT / PBM, 3);
    qkv_proj_kernel<<<gproj, 256>>>(x, Wq, bq, Wk, bk, Wv, bv);

    dim3 gattn(SEQ / 64, BATCH * NHEAD);
    attn_kernel<<<gattn, 256, ATTN_SMEM>>>();

    dim3 gout(EMBED / PBN, MTOT / PBM);
    out_proj_kernel<<<gout, 256>>>(Wo, bo, out);
}

// round 17
// speedup vs baseline: 1.2023x; 1.2023x over previous
#include <cuda_runtime.h>

// Round 17: attention QK+PV on bf16 double-split mma (m16n8k16, 3 terms,
// residual ~2^-18): halves attention HMMA count vs 3xTF32 (R16 showed tensor
// attention HMMA-count == a whole qkv GEMM; that floor is the invariant).
// k-pair u32 packing keeps fragment addressing identical to the proven tf32
// mapping. Projections = R11 exact (tf32, measured best).

#define EMBED 1024
#define NHEAD 16
#define HDIM  64
#define BATCH 2
#define SEQ   2048
#define MTOT  (BATCH*SEQ)

#define PBM 128
#define PBN 128
#define PBK 16
#define PADT 136

#define PADB 36      // u32 k-pairs per row (32 + pad)
#define PADS 68      // float stride for raw S
#define ATTN_FLOATS (6*64*PADB + 64*PADS + 128)
#define ATTN_SMEM   (ATTN_FLOATS*4)

typedef unsigned long long u64;
typedef unsigned int u32;
typedef unsigned short u16;

// ---- tf32 helpers (projections) ----
__device__ __forceinline__ void split_tf32(float a, u32& hi, u32& lo) {
    asm("cvt.rna.tf32.f32 %0, %1;" : "=r"(hi) : "f"(a));
    float r = a - __uint_as_float(hi);
    asm("cvt.rna.tf32.f32 %0, %1;" : "=r"(lo) : "f"(r));
}
__device__ __forceinline__ void mma8(float* c, const u32* a, const u32* b) {
    asm("mma.sync.aligned.m16n8k8.row.col.f32.tf32.tf32.f32 "
        "{%0,%1,%2,%3}, {%4,%5,%6,%7}, {%8,%9}, {%0,%1,%2,%3};"
        : "+f"(c[0]), "+f"(c[1]), "+f"(c[2]), "+f"(c[3])
        : "r"(a[0]), "r"(a[1]), "r"(a[2]), "r"(a[3]), "r"(b[0]), "r"(b[1]));
}

// ---- bf16 helpers (attention) ----
__device__ __forceinline__ u32 cvt2(float hi, float lo) {
    u32 r; asm("cvt.rn.satfinite.bf16x2.f32 %0, %1, %2;" : "=r"(r) : "f"(hi), "f"(lo));
    return r;
}
// pack pair (f0 -> lo16, f1 -> hi16) as bf16 hi-part + bf16 residual part
__device__ __forceinline__ void split2(float f0, float f1, u32& hp, u32& lp) {
    hp = cvt2(f1, f0);
    float f0h = __uint_as_float(hp << 16);
    float f1h = __uint_as_float(hp & 0xffff0000u);
    lp = cvt2(f1 - f1h, f0 - f0h);
}
__device__ __forceinline__ void mmab(float* c, const u32* a, const u32* b) {
    asm("mma.sync.aligned.m16n8k16.row.col.f32.bf16.bf16.f32 "
        "{%0,%1,%2,%3}, {%4,%5,%6,%7}, {%8,%9}, {%0,%1,%2,%3};"
        : "+f"(c[0]), "+f"(c[1]), "+f"(c[2]), "+f"(c[3])
        : "r"(a[0]), "r"(a[1]), "r"(a[2]), "r"(a[3]), "r"(b[0]), "r"(b[1]));
}

__device__ float g_q[BATCH*NHEAD*SEQ*HDIM];
__device__ float g_k[BATCH*NHEAD*SEQ*HDIM];
__device__ float g_v[BATCH*NHEAD*SEQ*HDIM];
__device__ float g_h[MTOT*EMBED];

// ---------------------------------------------------------------------------
// R11 projection GEMM body (measured best): split at STS time, scalar smem.
// ---------------------------------------------------------------------------
#define STS_SPLIT(DH, DL, J, V)                                                \
    { u32 _h, _l; split_tf32((V), _h, _l);                                     \
      DH[lc8+(J)][lr] = _h; DL[lc8+(J)][lr] = _l; }

#define PROJ_MMA_BODY(APTR, WPTR)                                              \
    __shared__ u32 Ash[PBK][PADT];                                             \
    __shared__ u32 Asl[PBK][PADT];                                             \
    __shared__ u32 Bsh[PBK][PADT];                                             \
    __shared__ u32 Bsl[PBK][PADT];                                             \
    const int tid  = threadIdx.x;                                              \
    const int lane = tid & 31;                                                 \
    const int wid  = tid >> 5;                                                 \
    const int m0 = blockIdx.y * PBM;                                           \
    const int n0 = blockIdx.x * PBN;                                           \
    const int wm = (wid >> 2) << 6;                                            \
    const int wn = (wid & 3) << 5;                                             \
    const int g4 = lane >> 2;                                                  \
    const int t4 = lane & 3;                                                   \
    const int lr  = tid >> 1;                                                  \
    const int lc8 = (tid & 1) << 3;                                            \
    const float* Ap = (APTR) + (size_t)(m0 + lr) * EMBED + lc8;                \
    const float* Wp = (WPTR) + (size_t)(n0 + lr) * EMBED + lc8;                \
    float c[4][4][4];                                                          \
    _Pragma("unroll")                                                          \
    for (int mi = 0; mi < 4; mi++)                                             \
        _Pragma("unroll")                                                      \
        for (int ni = 0; ni < 4; ni++)                                         \
            _Pragma("unroll")                                                  \
            for (int u = 0; u < 4; u++) c[mi][ni][u] = 0.f;                    \
    float4 a0 = *(const float4*)(Ap);                                          \
    float4 a1 = *(const float4*)(Ap + 4);                                      \
    float4 w0 = *(const float4*)(Wp);                                          \
    float4 w1 = *(const float4*)(Wp + 4);                                      \
    for (int kb = 0; kb < EMBED; kb += PBK) {                                  \
        __syncthreads();                                                       \
        STS_SPLIT(Ash, Asl, 0, a0.x)  STS_SPLIT(Ash, Asl, 1, a0.y)             \
        STS_SPLIT(Ash, Asl, 2, a0.z)  STS_SPLIT(Ash, Asl, 3, a0.w)             \
        STS_SPLIT(Ash, Asl, 4, a1.x)  STS_SPLIT(Ash, Asl, 5, a1.y)             \
        STS_SPLIT(Ash, Asl, 6, a1.z)  STS_SPLIT(Ash, Asl, 7, a1.w)             \
        STS_SPLIT(Bsh, Bsl, 0, w0.x)  STS_SPLIT(Bsh, Bsl, 1, w0.y)             \
        STS_SPLIT(Bsh, Bsl, 2, w0.z)  STS_SPLIT(Bsh, Bsl, 3, w0.w)             \
        STS_SPLIT(Bsh, Bsl, 4, w1.x)  STS_SPLIT(Bsh, Bsl, 5, w1.y)             \
        STS_SPLIT(Bsh, Bsl, 6, w1.z)  STS_SPLIT(Bsh, Bsl, 7, w1.w)             \
        __syncthreads();                                                       \
        if (kb + PBK < EMBED) {                                                \
            a0 = *(const float4*)(Ap + kb + PBK);                              \
            a1 = *(const float4*)(Ap + kb + PBK + 4);                          \
            w0 = *(const float4*)(Wp + kb + PBK);                              \
            w1 = *(const float4*)(Wp + kb + PBK + 4);                          \
        }                                                                      \
        _Pragma("unroll")                                                      \
        for (int k8 = 0; k8 < PBK; k8 += 8) {                                  \
            u32 bhi[4][2], blo[4][2];                                          \
            _Pragma("unroll")                                                  \
            for (int ni = 0; ni < 4; ni++) {                                   \
                const int kc = wn + ni*8 + g4;                                 \
                bhi[ni][0] = Bsh[k8 + t4    ][kc];                             \
                bhi[ni][1] = Bsh[k8 + t4 + 4][kc];                             \
                blo[ni][0] = Bsl[k8 + t4    ][kc];                             \
                blo[ni][1] = Bsl[k8 + t4 + 4][kc];                             \
            }                                                                  \
            _Pragma("unroll")                                                  \
            for (int mi = 0; mi < 4; mi++) {                                   \
                const int r = wm + mi*16 + g4;                                 \
                u32 ahi[4], alo[4];                                            \
                ahi[0] = Ash[k8 + t4    ][r];                                  \
                ahi[1] = Ash[k8 + t4    ][r + 8];                              \
                ahi[2] = Ash[k8 + t4 + 4][r];                                  \
                ahi[3] = Ash[k8 + t4 + 4][r + 8];                              \
                alo[0] = Asl[k8 + t4    ][r];                                  \
                alo[1] = Asl[k8 + t4    ][r + 8];                              \
                alo[2] = Asl[k8 + t4 + 4][r];                                  \
                alo[3] = Asl[k8 + t4 + 4][r + 8];                              \
                _Pragma("unroll")                                              \
                for (int ni = 0; ni < 4; ni++) {                               \
                    mma8(c[mi][ni], ahi, bhi[ni]);                             \
                    mma8(c[mi][ni], ahi, blo[ni]);                             \
                    mma8(c[mi][ni], alo, bhi[ni]);                             \
                }                                                              \
            }                                                                  \
        }                                                                      \
    }

// ---------------------------------------------------------------------------
__global__ __launch_bounds__(256, 2) void qkv_proj_kernel(
    const float* __restrict__ X,
    const float* __restrict__ Wq, const float* __restrict__ bq,
    const float* __restrict__ Wk, const float* __restrict__ bk,
    const float* __restrict__ Wv, const float* __restrict__ bv)
{
    const int z = blockIdx.z;
    const float *W, *bias; float* Out;
    if (z == 0)      { W = Wq; bias = bq; Out = g_q; }
    else if (z == 1) { W = Wk; bias = bk; Out = g_k; }
    else             { W = Wv; bias = bv; Out = g_v; }

    PROJ_MMA_BODY(X, W)

#pragma unroll
    for (int mi = 0; mi < 4; mi++) {
#pragma unroll
        for (int ni = 0; ni < 4; ni++) {
            const int col = n0 + wn + ni*8 + 2*t4;
            const int h   = col >> 6;
            const int d   = col & 63;
            float2 bb = *(const float2*)&bias[col];
#pragma unroll
            for (int half = 0; half < 2; half++) {
                int row = m0 + wm + mi*16 + g4 + half*8;
                int b   = row >> 11;
                int n   = row & (SEQ - 1);
                float2 o = make_float2(c[mi][ni][2*half+0] + bb.x,
                                       c[mi][ni][2*half+1] + bb.y);
                *(float2*)&Out[((size_t)(b*NHEAD + h)*SEQ + n)*HDIM + d] = o;
            }
        }
    }
}

// ---------------------------------------------------------------------------
__global__ __launch_bounds__(256, 2) void out_proj_kernel(
    const float* __restrict__ Wo, const float* __restrict__ bo,
    float* __restrict__ Outp)
{
    PROJ_MMA_BODY(g_h, Wo)

#pragma unroll
    for (int mi = 0; mi < 4; mi++) {
#pragma unroll
        for (int ni = 0; ni < 4; ni++) {
            const int col = n0 + wn + ni*8 + 2*t4;
            float2 bb = *(const float2*)&bo[col];
#pragma unroll
            for (int half = 0; half < 2; half++) {
                int row = m0 + wm + mi*16 + g4 + half*8;
                float2 o = make_float2(c[mi][ni][2*half+0] + bb.x,
                                       c[mi][ni][2*half+1] + bb.y);
                *(float2*)&Outp[(size_t)row * EMBED + col] = o;
            }
        }
    }
}

// ---------------------------------------------------------------------------
// bf16 double-split flash attention. Smem u32 pair-buffers [64][PADB]:
// Qh,Ql | KVh,KVl (K pairs along d; Vt pairs along key after QK) | Ph,Pl |
// Sf raw S floats | corr,l. 8 warps = 4(m) x 2(n). 4 barriers/tile.
// ---------------------------------------------------------------------------
__global__ __launch_bounds__(256, 2) void attn_kernel()
{
    extern __shared__ float sm[];
    u32*   Qh  = (u32*)sm;
    u32*   Ql  = (u32*)(sm + 1*64*PADB);
    u32*   KVh = (u32*)(sm + 2*64*PADB);
    u32*   KVl = (u32*)(sm + 3*64*PADB);
    u32*   Ph  = (u32*)(sm + 4*64*PADB);
    u32*   Pl  = (u32*)(sm + 5*64*PADB);
    float* Sf  = sm + 6*64*PADB;
    float* corr_s = sm + 6*64*PADB + 64*PADS;
    float* l_s    = corr_s + 64;

    const int tid  = threadIdx.x;
    const int lane = tid & 31;
    const int wid  = tid >> 5;
    const int bh  = blockIdx.y;
    const int q0  = blockIdx.x << 6;
    const size_t base = (size_t)bh * SEQ * HDIM;
    const float* Qg = g_q + base;
    const float* Kg = g_k + base;
    const float* Vg = g_v + base;

    const int lr = tid >> 2;           // staging row 0..63
    const int dq = (tid & 3) << 4;     // staging d-offset (16 elems)
    const int pb = (tid & 3) << 3;     // staging pair-offset (8 pairs)
    const int ty = tid >> 4;           // softmax mapping
    const int tx = tid & 15;
    const int qm0 = (wid >> 1) << 4;   // mma: warp q-row base
    const int wn  = (wid & 1) << 5;    // mma: warp n-half
    const int g4  = lane >> 2;
    const int t4  = lane & 3;

    // Stage Q once: fp32 load, bf16 double-split pairs -> Qh/Ql [q][pair]
#pragma unroll
    for (int it = 0; it < 4; it++) {
        float4 v = *(const float4*)&Qg[(size_t)(q0 + lr)*HDIM + dq + it*4];
        u32 h0, l0, h1, l1;
        split2(v.x, v.y, h0, l0);
        split2(v.z, v.w, h1, l1);
        *(uint2*)&Qh[lr*PADB + pb + it*2] = make_uint2(h0, h1);
        *(uint2*)&Ql[lr*PADB + pb + it*2] = make_uint2(l0, l1);
    }

    float m_run[4], l_run[4];
#pragma unroll
    for (int i = 0; i < 4; i++) { m_run[i] = -1e30f; l_run[i] = 0.f; }
    float co[4][4];
#pragma unroll
    for (int ni = 0; ni < 4; ni++)
#pragma unroll
        for (int u = 0; u < 4; u++) co[ni][u] = 0.f;

    for (int k0 = 0; k0 < SEQ; k0 += 64) {
        __syncthreads();   // (1) prev PV done; KV free
        // Stage K pairs along d
#pragma unroll
        for (int it = 0; it < 4; it++) {
            float4 v = *(const float4*)&Kg[(size_t)(k0 + lr)*HDIM + dq + it*4];
            u32 h0, l0, h1, l1;
            split2(v.x, v.y, h0, l0);
            split2(v.z, v.w, h1, l1);
            *(uint2*)&KVh[lr*PADB + pb + it*2] = make_uint2(h0, h1);
            *(uint2*)&KVl[lr*PADB + pb + it*2] = make_uint2(l0, l1);
        }
        __syncthreads();   // (2) K ready

        // ---- S = Q K^T via 3x bf16 mma (m16n8k16) ----
        float c[4][4];
#pragma unroll
        for (int ni = 0; ni < 4; ni++)
#pragma unroll
            for (int u = 0; u < 4; u++) c[ni][u] = 0.f;

#pragma unroll
        for (int s = 0; s < 4; s++) {
            const int bse = 8*s + t4;
            u32 ah[4], al[4];
            ah[0] = Qh[(qm0+g4  )*PADB + bse    ];
            ah[1] = Qh[(qm0+g4+8)*PADB + bse    ];
            ah[2] = Qh[(qm0+g4  )*PADB + bse + 4];
            ah[3] = Qh[(qm0+g4+8)*PADB + bse + 4];
            al[0] = Ql[(qm0+g4  )*PADB + bse    ];
            al[1] = Ql[(qm0+g4+8)*PADB + bse    ];
            al[2] = Ql[(qm0+g4  )*PADB + bse + 4];
            al[3] = Ql[(qm0+g4+8)*PADB + bse + 4];
#pragma unroll
            for (int ni = 0; ni < 4; ni++) {
                const int kr = wn + ni*8 + g4;
                u32 bhv[2], blv[2];
                bhv[0] = KVh[kr*PADB + bse];
                bhv[1] = KVh[kr*PADB + bse + 4];
                blv[0] = KVl[kr*PADB + bse];
                blv[1] = KVl[kr*PADB + bse + 4];
                mmab(c[ni], ah, bhv);
                mmab(c[ni], ah, blv);
                mmab(c[ni], al, bhv);
            }
        }
        // write raw S floats
#pragma unroll
        for (int ni = 0; ni < 4; ni++) {
            const int col = wn + ni*8 + 2*t4;
            *(float2*)&Sf[(qm0+g4  )*PADS + col] = make_float2(c[ni][0], c[ni][1]);
            *(float2*)&Sf[(qm0+g4+8)*PADS + col] = make_float2(c[ni][2], c[ni][3]);
        }
        __syncthreads();   // (3) S complete; K region free

        // ---- softmax -> split P pairs; stage Vt (transposed) into KV bufs ----
#pragma unroll
        for (int i = 0; i < 4; i++) {
            const int row = (ty<<2) + i;
            float4 sv = *(const float4*)&Sf[row*PADS + (tx<<2)];
            float s[4] = {sv.x*8.0f, sv.y*8.0f, sv.z*8.0f, sv.w*8.0f};
            float mx = fmaxf(fmaxf(s[0], s[1]), fmaxf(s[2], s[3]));
            mx = fmaxf(mx, __shfl_xor_sync(0xffffffffu, mx, 8, 16));
            mx = fmaxf(mx, __shfl_xor_sync(0xffffffffu, mx, 4, 16));
            mx = fmaxf(mx, __shfl_xor_sync(0xffffffffu, mx, 2, 16));
            mx = fmaxf(mx, __shfl_xor_sync(0xffffffffu, mx, 1, 16));
            float mnew = fmaxf(m_run[i], mx);
            float corr = __expf(m_run[i] - mnew);
            float p0 = __expf(s[0] - mnew);
            float p1 = __expf(s[1] - mnew);
            float p2 = __expf(s[2] - mnew);
            float p3 = __expf(s[3] - mnew);
            float rs = p0 + p1 + p2 + p3;
            rs += __shfl_xor_sync(0xffffffffu, rs, 8, 16);
            rs += __shfl_xor_sync(0xffffffffu, rs, 4, 16);
            rs += __shfl_xor_sync(0xffffffffu, rs, 2, 16);
            rs += __shfl_xor_sync(0xffffffffu, rs, 1, 16);
            l_run[i] = l_run[i] * corr + rs;
            m_run[i] = mnew;
            if (tx == 0) corr_s[row] = corr;
            u32 ph0, pl0, ph1, pl1;
            split2(p0, p1, ph0, pl0);
            split2(p2, p3, ph1, pl1);
            *(uint2*)&Ph[row*PADB + (tx<<1)] = make_uint2(ph0, ph1);
            *(uint2*)&Pl[row*PADB + (tx<<1)] = make_uint2(pl0, pl1);
        }
        // Vt: pairs along KEY -> 16-bit stores at [d][key]
        {
            u16* vth = (u16*)KVh;
            u16* vtl = (u16*)KVl;
#pragma unroll
            for (int it = 0; it < 4; it++) {
                float4 v = *(const float4*)&Vg[(size_t)(k0 + lr)*HDIM + dq + it*4];
                const int d0 = dq + it*4;
                u32 hp, lp;
                split2(v.x, v.y, hp, lp);
                vth[(d0+0)*(PADB*2) + lr] = (u16)(hp & 0xffffu);
                vth[(d0+1)*(PADB*2) + lr] = (u16)(hp >> 16);
                vtl[(d0+0)*(PADB*2) + lr] = (u16)(lp & 0xffffu);
                vtl[(d0+1)*(PADB*2) + lr] = (u16)(lp >> 16);
                split2(v.z, v.w, hp, lp);
                vth[(d0+2)*(PADB*2) + lr] = (u16)(hp & 0xffffu);
                vth[(d0+3)*(PADB*2) + lr] = (u16)(hp >> 16);
                vtl[(d0+2)*(PADB*2) + lr] = (u16)(lp & 0xffffu);
                vtl[(d0+3)*(PADB*2) + lr] = (u16)(lp >> 16);
            }
        }
        __syncthreads();   // (4) P pairs, corr, Vt ready

        // ---- O correction + O += P V via 3x bf16 mma ----
        {
            float c0 = corr_s[qm0 + g4];
            float c1 = corr_s[qm0 + g4 + 8];
#pragma unroll
            for (int ni = 0; ni < 4; ni++) {
                co[ni][0] *= c0; co[ni][1] *= c0;
                co[ni][2] *= c1; co[ni][3] *= c1;
            }
        }
#pragma unroll
        for (int s = 0; s < 4; s++) {
            const int bse = 8*s + t4;
            u32 ah[4], al[4];
            ah[0] = Ph[(qm0+g4  )*PADB + bse    ];
            ah[1] = Ph[(qm0+g4+8)*PADB + bse    ];
            ah[2] = Ph[(qm0+g4  )*PADB + bse + 4];
            ah[3] = Ph[(qm0+g4+8)*PADB + bse + 4];
            al[0] = Pl[(qm0+g4  )*PADB + bse    ];
            al[1] = Pl[(qm0+g4+8)*PADB + bse    ];
            al[2] = Pl[(qm0+g4  )*PADB + bse + 4];
            al[3] = Pl[(qm0+g4+8)*PADB + bse + 4];
#pragma unroll
            for (int ni = 0; ni < 4; ni++) {
                const int dr = wn + ni*8 + g4;
                u32 bhv[2], blv[2];
                bhv[0] = KVh[dr*PADB + bse];
                bhv[1] = KVh[dr*PADB + bse + 4];
                blv[0] = KVl[dr*PADB + bse];
                blv[1] = KVl[dr*PADB + bse + 4];
                mmab(co[ni], ah, bhv);
                mmab(co[ni], ah, blv);
                mmab(co[ni], al, bhv);
            }
        }
    }

    // publish l, write O normalized
    if (tx == 0) {
#pragma unroll
        for (int i = 0; i < 4; i++) l_s[(ty<<2)+i] = l_run[i];
    }
    __syncthreads();

    {
        const int b = bh >> 4;
        const int h = bh & 15;
        float inv0 = 1.0f / l_s[qm0 + g4];
        float inv1 = 1.0f / l_s[qm0 + g4 + 8];
        int r0 = q0 + qm0 + g4;
        int r1 = r0 + 8;
        float* dst0 = &g_h[((size_t)(b*SEQ + r0))*EMBED + h*HDIM];
        float* dst1 = &g_h[((size_t)(b*SEQ + r1))*EMBED + h*HDIM];
#pragma unroll
        for (int ni = 0; ni < 4; ni++) {
            const int col = wn + ni*8 + 2*t4;
            *(float2*)&dst0[col] = make_float2(co[ni][0]*inv0, co[ni][1]*inv0);
            *(float2*)&dst1[col] = make_float2(co[ni][2]*inv1, co[ni][3]*inv1);
        }
    }
}

// ---------------------------------------------------------------------------
extern "C" void kernel_launch(void* const* d_in, const int* in_sizes, int n_in,
                              void* d_out, int out_size)
{
    const float* x  = (const float*)d_in[0];
    const float* Wq = (const float*)d_in[1];
    const float* bq = (const float*)d_in[2];
    const float* Wk = (const float*)d_in[3];
    const float* bk = (const float*)d_in[4];
    const float* Wv = (const float*)d_in[5];
    const float* bv = (const float*)d_in[6];
    const float* Wo = (const float*)d_in[7];
    const float* bo = (const float*)d_in[8];
    float* out = (float*)d_out;

    cudaFuncSetAttribute(attn_kernel,
                         cudaFuncAttributeMaxDynamicSharedMemorySize, ATTN_SMEM);

    dim3 gproj(EMBED / PBN, MTOT / PBM, 3);
    qkv_proj_kernel<<<gproj, 256>>>(x, Wq, bq, Wk, bk, Wv, bv);

    dim3 gattn(SEQ / 64, BATCH * NHEAD);
    attn_kernel<<<gattn, 256, ATTN_SMEM>>>();

    dim3 gout(EMBED / PBN, MTOT / PBM);
    out_proj_kernel<<<gout, 256>>>(Wo, bo, out);
}